// round 10
// baseline (speedup 1.0000x reference)
#include <cuda_runtime.h>
#include <math.h>

#define NBODY 512
#define NVERT 6890
#define NJ 24
#define NCOL (NVERT*3)
#define KP 224               /* 207 pose + 10 beta + 1 template + 6 zero pad */
#define NTILE 216
#define NCOLPAD (NTILE*96)   /* 20736, col = v*3+c */
#define BN 64
#define BV 32

typedef unsigned long long ull;

// Scratch (device globals — no allocation anywhere)
__device__ float d_PextT[(size_t)KP * NCOLPAD]; // [k][col], col = v*3+c
__device__ float d_LextT[KP * NBODY];           // [k][body]
__device__ float2 d_Gm2[(NBODY/2) * NJ * 12];   // body-pair interleaved
__device__ float d_JS[NJ * 3 * 10];
__device__ float d_Jt[NJ * 3];

__constant__ int c_par[NJ] = {0,0,0,0,1,2,3,4,5,6,7,8,9,9,9,12,13,14,16,17,18,19,20,21};

// ---- packed f32x2 helpers -------------------------------------------------
__device__ __forceinline__ ull ffma2(ull a, ull b, ull c) {
    ull d;
    asm("fma.rn.f32x2 %0, %1, %2, %3;" : "=l"(d) : "l"(a), "l"(b), "l"(c));
    return d;
}
__device__ __forceinline__ ull dup2(float x) {
    ull d; unsigned u = __float_as_uint(x);
    asm("mov.b64 %0, {%1, %1};" : "=l"(d) : "r"(u));
    return d;
}
__device__ __forceinline__ float2 unpack2(ull p) {
    float2 r;
    asm("mov.b64 {%0, %1}, %2;" : "=f"(r.x), "=f"(r.y) : "l"(p));
    return r;
}
// ---- cp.async helpers ------------------------------------------------------
__device__ __forceinline__ void cp_async16(unsigned s, const void* g) {
    asm volatile("cp.async.cg.shared.global [%0], [%1], 16;\n" :: "r"(s), "l"(g));
}
__device__ __forceinline__ void cp_commit() {
    asm volatile("cp.async.commit_group;\n");
}
template<int N> __device__ __forceinline__ void cp_wait() {
    asm volatile("cp.async.wait_group %0;\n" :: "n"(N));
}

// ---------------------------------------------------------------------------
// Fused prep, grid 720 (unchanged from R8).
// ---------------------------------------------------------------------------
__global__ void __launch_bounds__(256)
prep_kernel(const float* __restrict__ posedirs,
            const float* __restrict__ shapedirs,
            const float* __restrict__ v_template,
            const float* __restrict__ Jreg)
{
    int bid = blockIdx.x;
    int tx = threadIdx.x, ty = threadIdx.y;
    if (bid < 648) {
        __shared__ float tile[32][229];
        int rbase = bid * 32;
        float r[28];
#pragma unroll
        for (int q = 0; q < 28; q++) {
            int kk0 = (q >> 2) * 32;
            int i = q & 3;
            int row = rbase + ty * 4 + i;
            int k = kk0 + tx;
            float v = 0.f;
            if (row < NCOL) {
                if (k < 207)       v = posedirs[row * 207 + k];
                else if (k < 217)  v = shapedirs[row * 10 + (k - 207)];
                else if (k == 217) v = v_template[row];
            }
            r[q] = v;
        }
#pragma unroll
        for (int q = 0; q < 28; q++) {
            int kk0 = (q >> 2) * 32;
            int i = q & 3;
            tile[ty * 4 + i][kk0 + tx] = r[q];
        }
        __syncthreads();
#pragma unroll
        for (int q = 0; q < 28; q++) {
            int k = q * 8 + ty;
            d_PextT[(size_t)k * NCOLPAD + rbase + tx] = tile[tx][k];
        }
    } else {
        int jc = bid - 648;
        int j = jc / 3, c = jc - j * 3;
        int tid = ty * 32 + tx;
        float acc[11];
#pragma unroll
        for (int q = 0; q < 11; q++) acc[q] = 0.f;
        for (int v = tid; v < NVERT; v += 256) {
            float jr = Jreg[j * NVERT + v];
            acc[0] += jr * v_template[v * 3 + c];
#pragma unroll
            for (int b = 0; b < 10; b++)
                acc[1 + b] += jr * shapedirs[(v * 3 + c) * 10 + b];
        }
        __shared__ float red[8][11];
        int lane = tid & 31, wid = tid >> 5;
#pragma unroll
        for (int q = 0; q < 11; q++) {
            float s = acc[q];
            for (int o = 16; o; o >>= 1) s += __shfl_down_sync(0xffffffffu, s, o);
            if (lane == 0) red[wid][q] = s;
        }
        __syncthreads();
        if (tid < 11) {
            int q = tid;
            float s = 0.f;
            for (int w = 0; w < 8; w++) s += red[w][q];
            if (q == 0) d_Jt[j * 3 + c] = s;
            else        d_JS[(j * 3 + c) * 10 + (q - 1)] = s;
        }
    }
}

// ---------------------------------------------------------------------------
// Per-body prep (unchanged from R8). 8 warps/block, 1 warp/body.
// ---------------------------------------------------------------------------
__global__ void __launch_bounds__(256)
body_kernel(const float* __restrict__ beta, const float* __restrict__ pose)
{
    int w = threadIdx.x >> 5;
    int lane = threadIdx.x & 31;
    int n = blockIdx.x * 8 + w;

    __shared__ float sR[8][NJ][9];
    __shared__ float sJ[8][NJ][3];
    __shared__ float sG[8][NJ][12];
    __shared__ float sBeta[8][10];

    if (lane < 10) sBeta[w][lane] = beta[n * 10 + lane];
    if (lane < NJ) {
        float x = pose[n * 72 + lane * 3 + 0];
        float y = pose[n * 72 + lane * 3 + 1];
        float z = pose[n * 72 + lane * 3 + 2];
        float th = sqrtf(x * x + y * y + z * z) + 1e-8f;
        float inv = 1.0f / th;
        x *= inv; y *= inv; z *= inv;
        float s, c;
        sincosf(th, &s, &c);
        float C = 1.0f - c;
        sR[w][lane][0] = c + C * x * x;     sR[w][lane][1] = C * x * y - s * z; sR[w][lane][2] = C * x * z + s * y;
        sR[w][lane][3] = C * x * y + s * z; sR[w][lane][4] = c + C * y * y;     sR[w][lane][5] = C * y * z - s * x;
        sR[w][lane][6] = C * x * z - s * y; sR[w][lane][7] = C * y * z + s * x; sR[w][lane][8] = c + C * z * z;
    }
    __syncwarp();

    for (int t = lane; t < 207; t += 32) {
        int jj = 1 + t / 9, e = t - (t / 9) * 9;
        d_LextT[t * NBODY + n] = sR[w][jj][e] - ((e == 0 || e == 4 || e == 8) ? 1.0f : 0.0f);
    }
    for (int t = lane; t < 17; t += 32) {
        int k = 207 + t;
        d_LextT[k * NBODY + n] = (t < 10) ? sBeta[w][t] : ((k == 217) ? 1.0f : 0.0f);
    }

    for (int t = lane; t < 72; t += 32) {
        int jj = t / 3, c = t - jj * 3;
        float s = d_Jt[jj * 3 + c];
#pragma unroll
        for (int b = 0; b < 10; b++) s += d_JS[(jj * 3 + c) * 10 + b] * sBeta[w][b];
        sJ[w][jj][c] = s;
    }
    __syncwarp();

    if (lane < 12) {
        int r = lane >> 2, cc = lane & 3;
        sG[w][0][lane] = (cc < 3) ? sR[w][0][r * 3 + cc] : sJ[w][0][r];
    }
    __syncwarp();
    for (int i = 1; i < NJ; i++) {
        int p = c_par[i];
        float val = 0.f;
        if (lane < 12) {
            int r = lane >> 2, cc = lane & 3;
            float t0, t1, t2;
            if (cc < 3) { t0 = sR[w][i][cc]; t1 = sR[w][i][3 + cc]; t2 = sR[w][i][6 + cc]; }
            else { t0 = sJ[w][i][0] - sJ[w][p][0]; t1 = sJ[w][i][1] - sJ[w][p][1]; t2 = sJ[w][i][2] - sJ[w][p][2]; }
            val = sG[w][p][r * 4 + 0] * t0 + sG[w][p][r * 4 + 1] * t1 + sG[w][p][r * 4 + 2] * t2;
            if (cc == 3) val += sG[w][p][r * 4 + 3];
        }
        __syncwarp();
        if (lane < 12) sG[w][i][lane] = val;
        __syncwarp();
    }

    for (int t = lane; t < 72; t += 32) {
        int jj = t / 3, r = t - jj * 3;
        float rj = sG[w][jj][r * 4 + 0] * sJ[w][jj][0] + sG[w][jj][r * 4 + 1] * sJ[w][jj][1]
                 + sG[w][jj][r * 4 + 2] * sJ[w][jj][2];
        sG[w][jj][r * 4 + 3] -= rj;
    }
    __syncwarp();
    for (int t = lane; t < NJ * 12; t += 32) {
        float g = sG[w][t / 12][t - (t / 12) * 12];
        if (n & 1) d_Gm2[(n >> 1) * (NJ * 12) + t].y = g;
        else       d_Gm2[(n >> 1) * (NJ * 12) + t].x = g;
    }
}

// ---------------------------------------------------------------------------
// Main fused kernel. 128 thr = 16 tx x 8 ty. Tile 64 bodies x 32 verts.
// Phase 1: cp.async double-buffered GEMM (unchanged inner loop).
// Phase 2: two passes of 2 body-pairs; 3-joint G chunks, double-buffered;
//          vp2 for q=2,3 spilled to smem between phases -> regs fit 5 blocks/SM.
// ---------------------------------------------------------------------------
#define AS_OFF(buf, kk, c) ((buf) * 2048 + (kk) * 64 + (c))
#define BS_OFF(buf, kk, c) (4096 + (buf) * 3200 + (kk) * 100 + (c))
#define G3_F2 1152     /* float2 per 3-joint G chunk: 32 pairs * 36 */
#define WS2_OFF 4608   /* floats: after 2 G chunk buffers (2*1152 float2) */
#define VPS_OFF 5408   /* floats: vp spill, 28 floats (112B) stride per thread */

__global__ void __launch_bounds__(128, 5)
smpl_main_kernel(const float* __restrict__ weights, float* __restrict__ out)
{
    __shared__ __align__(16) float smemf[10496];   // 42 KB

    float2* Gs2 = (float2*)smemf;
    float* Ws = smemf + WS2_OFF;

    int tid = threadIdx.x;
    int tx = tid & 15, ty = tid >> 4;
    int nBase = blockIdx.y * BN;
    int vBase = blockIdx.x * BV;
    int colBase = blockIdx.x * 96;
    int pBase = nBase >> 1;

    unsigned smem_base = (unsigned)__cvta_generic_to_shared(smemf);

    ull vp2[4][6];
#pragma unroll
    for (int p = 0; p < 4; p++)
#pragma unroll
        for (int j = 0; j < 6; j++) vp2[p][j] = 0ull;

    // ---- Phase 1 prologue ----
    {
#pragma unroll
        for (int t = 0; t < 4; t++) {
            int idx = tid + t * 128;
            int kk = idx >> 4, c4 = idx & 15;
            cp_async16(smem_base + AS_OFF(0, kk, c4 * 4) * 4,
                       &d_LextT[kk * NBODY + nBase + c4 * 4]);
        }
#pragma unroll
        for (int t = 0; t < 6; t++) {
            int idx = tid + t * 128;
            int kk = idx / 24, c4 = idx - kk * 24;
            cp_async16(smem_base + BS_OFF(0, kk, c4 * 4) * 4,
                       &d_PextT[(size_t)kk * NCOLPAD + colBase + c4 * 4]);
        }
        cp_commit();
    }

    for (int tt = 0; tt < 7; tt++) {
        int cur = tt & 1;
        if (tt < 6) {
            int nb = cur ^ 1;
            int k1 = (tt + 1) * 32;
#pragma unroll
            for (int t = 0; t < 4; t++) {
                int idx = tid + t * 128;
                int kk = idx >> 4, c4 = idx & 15;
                cp_async16(smem_base + AS_OFF(nb, kk, c4 * 4) * 4,
                           &d_LextT[(k1 + kk) * NBODY + nBase + c4 * 4]);
            }
#pragma unroll
            for (int t = 0; t < 6; t++) {
                int idx = tid + t * 128;
                int kk = idx / 24, c4 = idx - kk * 24;
                cp_async16(smem_base + BS_OFF(nb, kk, c4 * 4) * 4,
                           &d_PextT[(size_t)(k1 + kk) * NCOLPAD + colBase + c4 * 4]);
            }
            cp_commit();
            cp_wait<1>();
        } else {
            cp_wait<0>();
        }
        __syncthreads();

#pragma unroll
        for (int kk = 0; kk < 32; kk++) {
            ulonglong2 A0 = *(const ulonglong2*)&smemf[AS_OFF(cur, kk, ty * 8)];
            ulonglong2 A1 = *(const ulonglong2*)&smemf[AS_OFF(cur, kk, ty * 8 + 4)];
            float2 b01 = *(const float2*)&smemf[BS_OFF(cur, kk, tx * 6)];
            float2 b23 = *(const float2*)&smemf[BS_OFF(cur, kk, tx * 6 + 2)];
            float2 b45 = *(const float2*)&smemf[BS_OFF(cur, kk, tx * 6 + 4)];
            ull bd[6];
            bd[0] = dup2(b01.x); bd[1] = dup2(b01.y);
            bd[2] = dup2(b23.x); bd[3] = dup2(b23.y);
            bd[4] = dup2(b45.x); bd[5] = dup2(b45.y);
#pragma unroll
            for (int j = 0; j < 6; j++) {
                vp2[0][j] = ffma2(A0.x, bd[j], vp2[0][j]);
                vp2[1][j] = ffma2(A0.y, bd[j], vp2[1][j]);
                vp2[2][j] = ffma2(A1.x, bd[j], vp2[2][j]);
                vp2[3][j] = ffma2(A1.y, bd[j], vp2[3][j]);
            }
        }
        __syncthreads();
    }
    // all warps past final sync: phase-1 smem reusable

    // ---- Phase 2 prologue: spill vp2[2],vp2[3]; load Ws; prefetch G chunk 0 ----
    {
        ull* sp = (ull*)(smemf + VPS_OFF + tid * 28);
#pragma unroll
        for (int j = 0; j < 6; j++) { sp[j] = vp2[2][j]; sp[6 + j] = vp2[3][j]; }
    }
    for (int t = tid; t < BV * 24; t += 128) {
        int vl = t / 24, j2 = t - vl * 24;
        int v = vBase + vl;
        Ws[vl * 25 + j2] = (v < NVERT) ? weights[v * 24 + j2] : 0.f;
    }
#define PREF_G(buf, c8) do {                                                     \
    _Pragma("unroll")                                                            \
    for (int i = 0; i < 5; i++) {                                                \
        int t = tid + i * 128;                                                   \
        if (t < 576) {                                                           \
            int pl = t / 18, seg = t - pl * 18;                                  \
            cp_async16(smem_base + ((buf) * G3_F2 + pl * 36 + seg * 2) * 8,      \
                       &d_Gm2[(pBase + pl) * (NJ * 12) + (c8) * 36 + seg * 2]);  \
        }                                                                        \
    }                                                                            \
} while (0)
    PREF_G(0, 0);
    cp_commit();

    int stage = 0;
#pragma unroll
    for (int h = 0; h < 2; h++) {
        ull vpA[6], vpB[6];
        if (h == 0) {
#pragma unroll
            for (int j = 0; j < 6; j++) { vpA[j] = vp2[0][j]; vpB[j] = vp2[1][j]; }
        } else {
            const ull* sp = (const ull*)(smemf + VPS_OFF + tid * 28);
#pragma unroll
            for (int j = 0; j < 6; j++) { vpA[j] = sp[j]; vpB[j] = sp[6 + j]; }
        }
        ull oA[6], oB[6];
#pragma unroll
        for (int j = 0; j < 6; j++) { oA[j] = 0ull; oB[j] = 0ull; }

        for (int c8 = 0; c8 < 8; c8++, stage++) {
            int cur = stage & 1;
            if (stage < 15) {
                PREF_G(cur ^ 1, (stage + 1) & 7);
                cp_commit();
                cp_wait<1>();
            } else {
                cp_wait<0>();
            }
            __syncthreads();
#pragma unroll
            for (int jj = 0; jj < 3; jj++) {
                int jg = c8 * 3 + jj;
                ull w0 = dup2(Ws[(tx * 2) * 25 + jg]);
                ull w1 = dup2(Ws[(tx * 2 + 1) * 25 + jg]);
                const ull* gA = (const ull*)&Gs2[cur * G3_F2 + (ty * 4 + h * 2) * 36 + jj * 12];
                const ull* gB = (const ull*)&Gs2[cur * G3_F2 + (ty * 4 + h * 2 + 1) * 36 + jj * 12];
#pragma unroll
                for (int c = 0; c < 3; c++) {
                    ull g0 = gA[c * 4 + 0], g1 = gA[c * 4 + 1];
                    ull g2 = gA[c * 4 + 2], g3 = gA[c * 4 + 3];
                    ull t0 = ffma2(g0, vpA[0], ffma2(g1, vpA[1], ffma2(g2, vpA[2], g3)));
                    oA[c] = ffma2(w0, t0, oA[c]);
                    ull t1 = ffma2(g0, vpA[3], ffma2(g1, vpA[4], ffma2(g2, vpA[5], g3)));
                    oA[3 + c] = ffma2(w1, t1, oA[3 + c]);
                }
#pragma unroll
                for (int c = 0; c < 3; c++) {
                    ull g0 = gB[c * 4 + 0], g1 = gB[c * 4 + 1];
                    ull g2 = gB[c * 4 + 2], g3 = gB[c * 4 + 3];
                    ull t0 = ffma2(g0, vpB[0], ffma2(g1, vpB[1], ffma2(g2, vpB[2], g3)));
                    oB[c] = ffma2(w0, t0, oB[c]);
                    ull t1 = ffma2(g0, vpB[3], ffma2(g1, vpB[4], ffma2(g2, vpB[5], g3)));
                    oB[3 + c] = ffma2(w1, t1, oB[3 + c]);
                }
            }
            __syncthreads();
        }

        // ---- Store this pass's 2 body-pairs ----
#pragma unroll
        for (int qh = 0; qh < 2; qh++) {
            ull* o = (qh == 0) ? oA : oB;
            int n0 = nBase + ty * 8 + 2 * (h * 2 + qh);
#pragma unroll
            for (int vv = 0; vv < 2; vv++) {
                int v = vBase + tx * 2 + vv;
                if (v < NVERT) {
                    size_t b0 = ((size_t)n0 * NVERT + v) * 3;
                    size_t b1 = ((size_t)(n0 + 1) * NVERT + v) * 3;
#pragma unroll
                    for (int c = 0; c < 3; c++) {
                        float2 pr = unpack2(o[vv * 3 + c]);
                        out[b0 + c] = pr.x;
                        out[b1 + c] = pr.y;
                    }
                }
            }
        }
    }
}

// ---------------------------------------------------------------------------
extern "C" void kernel_launch(void* const* d_in, const int* in_sizes, int n_in,
                              void* d_out, int out_size)
{
    const float* beta        = (const float*)d_in[0];
    const float* pose        = (const float*)d_in[1];
    const float* v_template  = (const float*)d_in[2];
    const float* shapedirs   = (const float*)d_in[3];
    const float* posedirs    = (const float*)d_in[4];
    const float* J_regressor = (const float*)d_in[5];
    const float* weights     = (const float*)d_in[6];
    float* out = (float*)d_out;

    prep_kernel<<<720, dim3(32, 8)>>>(posedirs, shapedirs, v_template, J_regressor);
    body_kernel<<<NBODY / 8, 256>>>(beta, pose);
    smpl_main_kernel<<<dim3(NTILE, NBODY / BN), 128>>>(weights, out);
}

// round 11
// speedup vs baseline: 1.0380x; 1.0380x over previous
#include <cuda_runtime.h>
#include <math.h>

#define NBODY 512
#define NVERT 6890
#define NJ 24
#define NCOL (NVERT*3)
#define KP 224               /* 207 pose + 10 beta + 1 template + 6 zero pad */
#define NTILE 216
#define NCOLPAD (NTILE*96)   /* 20736, col = v*3+c */
#define BN 64
#define BV 32

typedef unsigned long long ull;

// Scratch (device globals — no allocation anywhere)
__device__ float d_PextT[(size_t)KP * NCOLPAD]; // [k][col], col = v*3+c
__device__ float d_LextT[KP * NBODY];           // [k][body]
__device__ float2 d_Gm2[(NBODY/2) * NJ * 12];   // body-pair interleaved
__device__ float d_JS[NJ * 3 * 10];
__device__ float d_Jt[NJ * 3];

__constant__ int c_par[NJ] = {0,0,0,0,1,2,3,4,5,6,7,8,9,9,9,12,13,14,16,17,18,19,20,21};

// ---- packed f32x2 helpers -------------------------------------------------
__device__ __forceinline__ ull ffma2(ull a, ull b, ull c) {
    ull d;
    asm("fma.rn.f32x2 %0, %1, %2, %3;" : "=l"(d) : "l"(a), "l"(b), "l"(c));
    return d;
}
__device__ __forceinline__ ull dup2(float x) {
    ull d; unsigned u = __float_as_uint(x);
    asm("mov.b64 %0, {%1, %1};" : "=l"(d) : "r"(u));
    return d;
}
__device__ __forceinline__ float2 unpack2(ull p) {
    float2 r;
    asm("mov.b64 {%0, %1}, %2;" : "=f"(r.x), "=f"(r.y) : "l"(p));
    return r;
}
// ---- cp.async helpers ------------------------------------------------------
__device__ __forceinline__ void cp_async16(unsigned s, const void* g) {
    asm volatile("cp.async.cg.shared.global [%0], [%1], 16;\n" :: "r"(s), "l"(g));
}
__device__ __forceinline__ void cp_commit() {
    asm volatile("cp.async.commit_group;\n");
}
template<int N> __device__ __forceinline__ void cp_wait() {
    asm volatile("cp.async.wait_group %0;\n" :: "n"(N));
}

// ---------------------------------------------------------------------------
// Transpose one 32-col strip over NK k-values starting at kbase.
// tile stride 129 (odd mod 32) -> conflict-free transposed reads.
// ---------------------------------------------------------------------------
template<int NK>
__device__ __forceinline__ void transpose_strip(
    const float* __restrict__ posedirs,
    const float* __restrict__ shapedirs,
    const float* __restrict__ v_template,
    float (*tile)[129], int rbase, int kbase, int tx, int ty)
{
    float r[NK / 8];
#pragma unroll
    for (int q = 0; q < NK / 8; q++) {
        int kl = (q >> 2) * 32 + tx;
        int row = rbase + (q & 3) * 8 + ty;
        int k = kbase + kl;
        float v = 0.f;
        if (row < NCOL) {
            if (k < 207)       v = posedirs[row * 207 + k];
            else if (k < 217)  v = shapedirs[row * 10 + (k - 207)];
            else if (k == 217) v = v_template[row];
        }
        r[q] = v;
    }
#pragma unroll
    for (int q = 0; q < NK / 8; q++) {
        int kl = (q >> 2) * 32 + tx;
        int row = (q & 3) * 8 + ty;
        tile[row][kl] = r[q];
    }
    __syncthreads();
#pragma unroll
    for (int q = 0; q < NK / 8; q++) {
        int kl = q * 8 + ty;
        d_PextT[(size_t)(kbase + kl) * NCOLPAD + rbase + tx] = tile[tx][kl];
    }
}

// ---------------------------------------------------------------------------
// Fused prep, grid 1368:
//  blocks [0,1296): transpose; strip = bid>>1, k-half = bid&1 (128 / 96 k's).
//  blocks [1296,1368): fold J_regressor into shape space (72 = joint*coord).
// blockDim = (32,8).
// ---------------------------------------------------------------------------
__global__ void __launch_bounds__(256)
prep_kernel(const float* __restrict__ posedirs,
            const float* __restrict__ shapedirs,
            const float* __restrict__ v_template,
            const float* __restrict__ Jreg)
{
    int bid = blockIdx.x;
    int tx = threadIdx.x, ty = threadIdx.y;
    if (bid < 1296) {
        __shared__ float tile[32][129];
        int rbase = (bid >> 1) * 32;
        if ((bid & 1) == 0)
            transpose_strip<128>(posedirs, shapedirs, v_template, tile, rbase, 0, tx, ty);
        else
            transpose_strip<96>(posedirs, shapedirs, v_template, tile, rbase, 128, tx, ty);
    } else {
        int jc = bid - 1296;
        int j = jc / 3, c = jc - j * 3;
        int tid = ty * 32 + tx;
        float acc[11];
#pragma unroll
        for (int q = 0; q < 11; q++) acc[q] = 0.f;
        for (int v = tid; v < NVERT; v += 256) {
            float jr = Jreg[j * NVERT + v];
            acc[0] += jr * v_template[v * 3 + c];
#pragma unroll
            for (int b = 0; b < 10; b++)
                acc[1 + b] += jr * shapedirs[(v * 3 + c) * 10 + b];
        }
        __shared__ float red[8][11];
        int lane = tid & 31, wid = tid >> 5;
#pragma unroll
        for (int q = 0; q < 11; q++) {
            float s = acc[q];
            for (int o = 16; o; o >>= 1) s += __shfl_down_sync(0xffffffffu, s, o);
            if (lane == 0) red[wid][q] = s;
        }
        __syncthreads();
        if (tid < 11) {
            int q = tid;
            float s = 0.f;
            for (int w = 0; w < 8; w++) s += red[w][q];
            if (q == 0) d_Jt[j * 3 + c] = s;
            else        d_JS[(j * 3 + c) * 10 + (q - 1)] = s;
        }
    }
}

// ---------------------------------------------------------------------------
// Per-body prep (unchanged). 8 warps/block, 1 warp/body.
// ---------------------------------------------------------------------------
__global__ void __launch_bounds__(256)
body_kernel(const float* __restrict__ beta, const float* __restrict__ pose)
{
    int w = threadIdx.x >> 5;
    int lane = threadIdx.x & 31;
    int n = blockIdx.x * 8 + w;

    __shared__ float sR[8][NJ][9];
    __shared__ float sJ[8][NJ][3];
    __shared__ float sG[8][NJ][12];
    __shared__ float sBeta[8][10];

    if (lane < 10) sBeta[w][lane] = beta[n * 10 + lane];
    if (lane < NJ) {
        float x = pose[n * 72 + lane * 3 + 0];
        float y = pose[n * 72 + lane * 3 + 1];
        float z = pose[n * 72 + lane * 3 + 2];
        float th = sqrtf(x * x + y * y + z * z) + 1e-8f;
        float inv = 1.0f / th;
        x *= inv; y *= inv; z *= inv;
        float s, c;
        sincosf(th, &s, &c);
        float C = 1.0f - c;
        sR[w][lane][0] = c + C * x * x;     sR[w][lane][1] = C * x * y - s * z; sR[w][lane][2] = C * x * z + s * y;
        sR[w][lane][3] = C * x * y + s * z; sR[w][lane][4] = c + C * y * y;     sR[w][lane][5] = C * y * z - s * x;
        sR[w][lane][6] = C * x * z - s * y; sR[w][lane][7] = C * y * z + s * x; sR[w][lane][8] = c + C * z * z;
    }
    __syncwarp();

    for (int t = lane; t < 207; t += 32) {
        int jj = 1 + t / 9, e = t - (t / 9) * 9;
        d_LextT[t * NBODY + n] = sR[w][jj][e] - ((e == 0 || e == 4 || e == 8) ? 1.0f : 0.0f);
    }
    for (int t = lane; t < 17; t += 32) {
        int k = 207 + t;
        d_LextT[k * NBODY + n] = (t < 10) ? sBeta[w][t] : ((k == 217) ? 1.0f : 0.0f);
    }

    for (int t = lane; t < 72; t += 32) {
        int jj = t / 3, c = t - jj * 3;
        float s = d_Jt[jj * 3 + c];
#pragma unroll
        for (int b = 0; b < 10; b++) s += d_JS[(jj * 3 + c) * 10 + b] * sBeta[w][b];
        sJ[w][jj][c] = s;
    }
    __syncwarp();

    if (lane < 12) {
        int r = lane >> 2, cc = lane & 3;
        sG[w][0][lane] = (cc < 3) ? sR[w][0][r * 3 + cc] : sJ[w][0][r];
    }
    __syncwarp();
    for (int i = 1; i < NJ; i++) {
        int p = c_par[i];
        float val = 0.f;
        if (lane < 12) {
            int r = lane >> 2, cc = lane & 3;
            float t0, t1, t2;
            if (cc < 3) { t0 = sR[w][i][cc]; t1 = sR[w][i][3 + cc]; t2 = sR[w][i][6 + cc]; }
            else { t0 = sJ[w][i][0] - sJ[w][p][0]; t1 = sJ[w][i][1] - sJ[w][p][1]; t2 = sJ[w][i][2] - sJ[w][p][2]; }
            val = sG[w][p][r * 4 + 0] * t0 + sG[w][p][r * 4 + 1] * t1 + sG[w][p][r * 4 + 2] * t2;
            if (cc == 3) val += sG[w][p][r * 4 + 3];
        }
        __syncwarp();
        if (lane < 12) sG[w][i][lane] = val;
        __syncwarp();
    }

    for (int t = lane; t < 72; t += 32) {
        int jj = t / 3, r = t - jj * 3;
        float rj = sG[w][jj][r * 4 + 0] * sJ[w][jj][0] + sG[w][jj][r * 4 + 1] * sJ[w][jj][1]
                 + sG[w][jj][r * 4 + 2] * sJ[w][jj][2];
        sG[w][jj][r * 4 + 3] -= rj;
    }
    __syncwarp();
    for (int t = lane; t < NJ * 12; t += 32) {
        float g = sG[w][t / 12][t - (t / 12) * 12];
        if (n & 1) d_Gm2[(n >> 1) * (NJ * 12) + t].y = g;
        else       d_Gm2[(n >> 1) * (NJ * 12) + t].x = g;
    }
}

// ---------------------------------------------------------------------------
// Main fused kernel — EXACT R8 shape (best passing: 179.3us total).
// 128 thr = 16 tx x 8 ty. Tile 64 bodies x 32 verts.
// ---------------------------------------------------------------------------
#define AS_OFF(buf, kk, c) ((buf) * 2048 + (kk) * 64 + (c))
#define BS_OFF(buf, kk, c) (4096 + (buf) * 3200 + (kk) * 100 + (c))
#define GS_STRIDE 74
#define GBUF_F2 2368
#define WS_OFF 9472

__global__ void __launch_bounds__(128, 4)
smpl_main_kernel(const float* __restrict__ weights, float* __restrict__ out)
{
    __shared__ __align__(16) float smemf[10496];   // 42 KB

    float2* Gs2 = (float2*)smemf;
    float* Ws = smemf + WS_OFF;

    int tid = threadIdx.x;
    int tx = tid & 15, ty = tid >> 4;
    int nBase = blockIdx.y * BN;
    int vBase = blockIdx.x * BV;
    int colBase = blockIdx.x * 96;
    int pBase = nBase >> 1;

    unsigned smem_base = (unsigned)__cvta_generic_to_shared(smemf);

    ull vp2[4][6];
#pragma unroll
    for (int p = 0; p < 4; p++)
#pragma unroll
        for (int j = 0; j < 6; j++) vp2[p][j] = 0ull;

    {
#pragma unroll
        for (int t = 0; t < 4; t++) {
            int idx = tid + t * 128;
            int kk = idx >> 4, c4 = idx & 15;
            cp_async16(smem_base + AS_OFF(0, kk, c4 * 4) * 4,
                       &d_LextT[kk * NBODY + nBase + c4 * 4]);
        }
#pragma unroll
        for (int t = 0; t < 6; t++) {
            int idx = tid + t * 128;
            int kk = idx / 24, c4 = idx - kk * 24;
            cp_async16(smem_base + BS_OFF(0, kk, c4 * 4) * 4,
                       &d_PextT[(size_t)kk * NCOLPAD + colBase + c4 * 4]);
        }
        cp_commit();
    }

    for (int tt = 0; tt < 7; tt++) {
        int cur = tt & 1;
        if (tt < 6) {
            int nb = cur ^ 1;
            int k1 = (tt + 1) * 32;
#pragma unroll
            for (int t = 0; t < 4; t++) {
                int idx = tid + t * 128;
                int kk = idx >> 4, c4 = idx & 15;
                cp_async16(smem_base + AS_OFF(nb, kk, c4 * 4) * 4,
                           &d_LextT[(k1 + kk) * NBODY + nBase + c4 * 4]);
            }
#pragma unroll
            for (int t = 0; t < 6; t++) {
                int idx = tid + t * 128;
                int kk = idx / 24, c4 = idx - kk * 24;
                cp_async16(smem_base + BS_OFF(nb, kk, c4 * 4) * 4,
                           &d_PextT[(size_t)(k1 + kk) * NCOLPAD + colBase + c4 * 4]);
            }
            cp_commit();
            cp_wait<1>();
        } else {
            cp_wait<0>();
        }
        __syncthreads();

#pragma unroll
        for (int kk = 0; kk < 32; kk++) {
            ulonglong2 A0 = *(const ulonglong2*)&smemf[AS_OFF(cur, kk, ty * 8)];
            ulonglong2 A1 = *(const ulonglong2*)&smemf[AS_OFF(cur, kk, ty * 8 + 4)];
            float2 b01 = *(const float2*)&smemf[BS_OFF(cur, kk, tx * 6)];
            float2 b23 = *(const float2*)&smemf[BS_OFF(cur, kk, tx * 6 + 2)];
            float2 b45 = *(const float2*)&smemf[BS_OFF(cur, kk, tx * 6 + 4)];
            ull bd[6];
            bd[0] = dup2(b01.x); bd[1] = dup2(b01.y);
            bd[2] = dup2(b23.x); bd[3] = dup2(b23.y);
            bd[4] = dup2(b45.x); bd[5] = dup2(b45.y);
#pragma unroll
            for (int j = 0; j < 6; j++) {
                vp2[0][j] = ffma2(A0.x, bd[j], vp2[0][j]);
                vp2[1][j] = ffma2(A0.y, bd[j], vp2[1][j]);
                vp2[2][j] = ffma2(A1.x, bd[j], vp2[2][j]);
                vp2[3][j] = ffma2(A1.y, bd[j], vp2[3][j]);
            }
        }
        __syncthreads();
    }

    // ---- Phase 2 prologue: prefetch G chunk 0, load Ws ----
    {
#pragma unroll
        for (int i = 0; i < 9; i++) {
            int t = tid + i * 128;
            int pl = t / 36, seg = t - pl * 36;
            cp_async16(smem_base + (pl * GS_STRIDE + seg * 2) * 8,
                       &d_Gm2[(pBase + pl) * (NJ * 12) + seg * 2]);
        }
        cp_commit();
    }
    for (int t = tid; t < BV * 24; t += 128) {
        int vl = t / 24, j2 = t - vl * 24;
        int v = vBase + vl;
        Ws[vl * 25 + j2] = (v < NVERT) ? weights[v * 24 + j2] : 0.f;
    }

    ull o2[4][6];
#pragma unroll
    for (int p = 0; p < 4; p++)
#pragma unroll
        for (int j = 0; j < 6; j++) o2[p][j] = 0ull;

    for (int jc = 0; jc < 4; jc++) {
        int cur = jc & 1;
        if (jc < 3) {
            int nb = cur ^ 1;
#pragma unroll
            for (int i = 0; i < 9; i++) {
                int t = tid + i * 128;
                int pl = t / 36, seg = t - pl * 36;
                cp_async16(smem_base + (nb * GBUF_F2 + pl * GS_STRIDE + seg * 2) * 8,
                           &d_Gm2[(pBase + pl) * (NJ * 12) + (jc + 1) * 72 + seg * 2]);
            }
            cp_commit();
            cp_wait<1>();
        } else {
            cp_wait<0>();
        }
        __syncthreads();
#pragma unroll
        for (int jj = 0; jj < 6; jj++) {
            ull w0 = dup2(Ws[(tx * 2) * 25 + jc * 6 + jj]);
            ull w1 = dup2(Ws[(tx * 2 + 1) * 25 + jc * 6 + jj]);
#pragma unroll
            for (int q = 0; q < 4; q++) {
                const ull* g = (const ull*)&Gs2[cur * GBUF_F2 + (ty * 4 + q) * GS_STRIDE + jj * 12];
#pragma unroll
                for (int c = 0; c < 3; c++) {
                    ull g0 = g[c * 4 + 0], g1 = g[c * 4 + 1];
                    ull g2 = g[c * 4 + 2], g3 = g[c * 4 + 3];
                    ull t0 = ffma2(g0, vp2[q][0], ffma2(g1, vp2[q][1], ffma2(g2, vp2[q][2], g3)));
                    o2[q][c] = ffma2(w0, t0, o2[q][c]);
                    ull t1 = ffma2(g0, vp2[q][3], ffma2(g1, vp2[q][4], ffma2(g2, vp2[q][5], g3)));
                    o2[q][3 + c] = ffma2(w1, t1, o2[q][3 + c]);
                }
            }
        }
        __syncthreads();
    }

    // ---- Store ----
#pragma unroll
    for (int q = 0; q < 4; q++) {
        int n0 = nBase + ty * 8 + 2 * q;
#pragma unroll
        for (int vv = 0; vv < 2; vv++) {
            int v = vBase + tx * 2 + vv;
            if (v < NVERT) {
                size_t b0 = ((size_t)n0 * NVERT + v) * 3;
                size_t b1 = ((size_t)(n0 + 1) * NVERT + v) * 3;
#pragma unroll
                for (int c = 0; c < 3; c++) {
                    float2 pr = unpack2(o2[q][vv * 3 + c]);
                    out[b0 + c] = pr.x;
                    out[b1 + c] = pr.y;
                }
            }
        }
    }
}

// ---------------------------------------------------------------------------
extern "C" void kernel_launch(void* const* d_in, const int* in_sizes, int n_in,
                              void* d_out, int out_size)
{
    const float* beta        = (const float*)d_in[0];
    const float* pose        = (const float*)d_in[1];
    const float* v_template  = (const float*)d_in[2];
    const float* shapedirs   = (const float*)d_in[3];
    const float* posedirs    = (const float*)d_in[4];
    const float* J_regressor = (const float*)d_in[5];
    const float* weights     = (const float*)d_in[6];
    float* out = (float*)d_out;

    prep_kernel<<<1368, dim3(32, 8)>>>(posedirs, shapedirs, v_template, J_regressor);
    body_kernel<<<NBODY / 8, 256>>>(beta, pose);
    smpl_main_kernel<<<dim3(NTILE, NBODY / BN), 128>>>(weights, out);
}